// round 16
// baseline (speedup 1.0000x reference)
#include <cuda_runtime.h>
#include <cstdint>
#include <cstddef>

#define CINC  3
#define WARPS 4
#define MB    16               // batches per warp (one m16 tile)
#define CTAB  (WARPS * MB)     // 64
#define NTH   (WARPS * 32)

// ---- smem layout (bytes); B-fragments packed as kt-pairs ----
#define BF1_OFF 0              // 8192
#define BF2_OFF 8192           // 16384
#define BF3_OFF 24576          // 24576
#define B1E_OFF 49152          // 2048
#define B2E_OFF 51200          // 2048
#define B3E_OFF 53248          // 3072
#define SMEM_BYTES 56320

__device__ __forceinline__ float hi16f(uint32_t u) { return __uint_as_float(u & 0xFFFF0000u); }

__device__ __forceinline__ uint32_t bf_plane(float v, int p) {
    uint32_t u = __float_as_uint(v);
    if (p == 0) return u >> 16;
    float r = v - hi16f(u);
    return __float_as_uint(r) >> 16;
}

__device__ __forceinline__ void split_pair(float va, float vb, uint32_t& p0, uint32_t& p1) {
    uint32_t Aa = __float_as_uint(va), Ab = __float_as_uint(vb);
    float ra = va - hi16f(Aa), rb = vb - hi16f(Ab);
    uint32_t Ra = __float_as_uint(ra), Rb = __float_as_uint(rb);
    p0 = __byte_perm(Aa, Ab, 0x7632);
    p1 = __byte_perm(Ra, Rb, 0x7632);
}

// tanh with a single MUFU (RCP): e^{2x} built from FFMA-only 2^t evaluation.
// t = 2x*log2(e); n = round(t) via magic-constant; 2^f poly (deg 5, |f|<=0.5);
// exponent applied by integer add into float bits; tanh = 1 - 2/(e+1).
__device__ __forceinline__ float fast_tanh(float x) {
    float t = x * 2.8853900817779268f;                 // 2*log2(e)
    t = fminf(fmaxf(t, -125.0f), 125.0f);
    float k = t + 12582912.0f;                          // 1.5*2^23 round-to-int
    int n = __float_as_int(k) - 0x4B400000;
    float f = t - (k - 12582912.0f);                    // f in [-0.5, 0.5]
    float p = 0.0013333558146f;
    p = fmaf(p, f, 0.0096181291076f);
    p = fmaf(p, f, 0.0555041086648f);
    p = fmaf(p, f, 0.2402265069591f);
    p = fmaf(p, f, 0.6931471805599f);
    p = fmaf(p, f, 1.0f);
    float e = __int_as_float(__float_as_int(p) + (n << 23));   // e^{2x}
    float r;
    asm("rcp.approx.f32 %0, %1;" : "=f"(r) : "f"(e + 1.0f));
    return fmaf(-2.0f, r, 1.0f);
}

__device__ __forceinline__ void mma_bf16(float* d, const uint32_t* a, uint32_t b0, uint32_t b1) {
    asm volatile("mma.sync.aligned.m16n8k16.row.col.f32.bf16.bf16.f32 "
                 "{%0,%1,%2,%3}, {%4,%5,%6,%7}, {%8,%9}, {%0,%1,%2,%3};"
                 : "+f"(d[0]), "+f"(d[1]), "+f"(d[2]), "+f"(d[3])
                 : "r"(a[0]), "r"(a[1]), "r"(a[2]), "r"(a[3]), "r"(b0), "r"(b1));
}

__global__ void __launch_bounds__(NTH, 2) cde_hmma_kernel(
    const float* __restrict__ times,
    const float* __restrict__ grads,
    const float* __restrict__ w1, const float* __restrict__ b1,
    const float* __restrict__ w2, const float* __restrict__ b2,
    const float* __restrict__ w3, const float* __restrict__ b3,
    const float* __restrict__ w_enc, const float* __restrict__ b_enc,
    const float* __restrict__ w_ro, const float* __restrict__ b_ro,
    float* __restrict__ out, int B, int T)
{
    extern __shared__ char sm[];
    int tid = threadIdx.x;
    int lane = tid & 31, warp = tid >> 5;

    // ---- Build packed B-fragment planes + expanded biases in smem ----
    for (int idx = tid; idx < 2 * 8 * 2 * 32; idx += NTH) {
        int ln = idx & 31, f = idx >> 5;
        int kt = f % 2, nt = (f / 2) % 8, p = f / 16;
        int n = nt * 8 + ln / 4, k0 = kt * 16 + 2 * (ln & 3);
        const float* wr = w1 + n * 32;
        uint32_t l0 = bf_plane(wr[k0], p),     l1 = bf_plane(wr[k0 + 1], p);
        uint32_t h0 = bf_plane(wr[k0 + 8], p), h1 = bf_plane(wr[k0 + 9], p);
        ((uint2*)(sm + BF1_OFF))[((p * 8 + nt) * 32 + ln) * 2 + kt] =
            make_uint2(l0 | (l1 << 16), h0 | (h1 << 16));
    }
    for (int idx = tid; idx < 2 * 8 * 4 * 32; idx += NTH) {
        int ln = idx & 31, f = idx >> 5;
        int kt = f % 4, nt = (f / 4) % 8, p = f / 32;
        int n = nt * 8 + ln / 4, k0 = kt * 16 + 2 * (ln & 3);
        const float* wr = w2 + n * 64;
        uint32_t l0 = bf_plane(wr[k0], p),     l1 = bf_plane(wr[k0 + 1], p);
        uint32_t h0 = bf_plane(wr[k0 + 8], p), h1 = bf_plane(wr[k0 + 9], p);
        ((uint2*)(sm + BF2_OFF))[(((p * 8 + nt) * 2 + (kt >> 1)) * 32 + ln) * 2 + (kt & 1)] =
            make_uint2(l0 | (l1 << 16), h0 | (h1 << 16));
    }
    for (int idx = tid; idx < 2 * 12 * 4 * 32; idx += NTH) {
        int ln = idx & 31, f = idx >> 5;
        int kt = f % 4, nt = (f / 4) % 12, p = f / 48;
        int np = nt * 8 + ln / 4;
        int row = 3 * (np & 31) + (np >> 5);      // permuted: logical n' = h + 32*ch
        int k0 = kt * 16 + 2 * (ln & 3);
        const float* wr = w3 + row * 64;
        uint32_t l0 = bf_plane(wr[k0], p),     l1 = bf_plane(wr[k0 + 1], p);
        uint32_t h0 = bf_plane(wr[k0 + 8], p), h1 = bf_plane(wr[k0 + 9], p);
        ((uint2*)(sm + BF3_OFF))[(((p * 12 + nt) * 2 + (kt >> 1)) * 32 + ln) * 2 + (kt & 1)] =
            make_uint2(l0 | (l1 << 16), h0 | (h1 << 16));
    }
    for (int idx = tid; idx < 8 * 32; idx += NTH) {
        int ln = idx & 31, nt = idx >> 5;
        int c = 8 * nt + 2 * (ln & 3);
        ((float2*)(sm + B1E_OFF))[idx] = make_float2(b1[c], b1[c + 1]);
        ((float2*)(sm + B2E_OFF))[idx] = make_float2(b2[c], b2[c + 1]);
    }
    for (int idx = tid; idx < 12 * 32; idx += NTH) {
        int ln = idx & 31, nt = idx >> 5;
        int c = 8 * nt + 2 * (ln & 3);
        int i0 = 3 * (c & 31) + (c >> 5);
        int c1v = c + 1;
        int i1 = 3 * (c1v & 31) + (c1v >> 5);
        ((float2*)(sm + B3E_OFF))[idx] = make_float2(b3[i0], b3[i1]);
    }
    __syncthreads();

    const uint4* bf1 = (const uint4*)(sm + BF1_OFF);
    const uint4* bf2 = (const uint4*)(sm + BF2_OFF);
    const uint4* bf3 = (const uint4*)(sm + BF3_OFF);
    const float2* be1 = (const float2*)(sm + B1E_OFF);
    const float2* be2 = (const float2*)(sm + B2E_OFF);
    const float2* be3 = (const float2*)(sm + B3E_OFF);

    int base = blockIdx.x * CTAB + warp * MB;
    int bA = base + (lane >> 2);
    int bB = bA + 8;
    bool vA = bA < B, vB = bB < B;
    const float* gA = grads + (size_t)(vA ? bA : 0) * (size_t)T * CINC;
    const float* gB = grads + (size_t)(vB ? bB : 0) * (size_t)T * CINC;

    float dt = times[1] - times[0];

    float z[16], k1[16], k2[16], k3[16], k4[16], k5[16], zs[16];
#pragma unroll
    for (int t = 0; t < 4; t++) {
        int c = 8 * t + 2 * (lane & 3);
        float v0 = w_enc[c] + b_enc[c];
        float v1 = w_enc[c + 1] + b_enc[c + 1];
        z[t * 4 + 0] = v0; z[t * 4 + 1] = v1; z[t * 4 + 2] = v0; z[t * 4 + 3] = v1;
    }

    uint32_t As[2][4][4], An[2][4][4];

    float pgA[3], pgB[3];
#pragma unroll
    for (int c = 0; c < 3; c++) { pgA[c] = gA[c]; pgB[c] = gB[c]; }

#pragma unroll 1
    for (int n = 0; n < T - 1; n++) {
        float dqA[3], dqB[3];
#pragma unroll
        for (int c = 0; c < 3; c++) { dqA[c] = pgA[c] * dt; dqB[c] = pgB[c] * dt; }
        int np = (n + 1 < T - 1) ? (n + 1) : n;
#pragma unroll
        for (int c = 0; c < 3; c++) { pgA[c] = gA[np * 3 + c]; pgB[c] = gB[np * 3 + c]; }

#pragma unroll
        for (int i = 0; i < 16; i++) zs[i] = z[i];

#pragma unroll 1
        for (int s = 0; s < 6; s++) {
            // A1 fragments (ktiles 0,1) from zs; lane-local
#pragma unroll
            for (int j = 0; j < 2; j++) {
                split_pair(zs[(2 * j) * 4 + 0], zs[(2 * j) * 4 + 1], As[0][j][0], As[1][j][0]);
                split_pair(zs[(2 * j) * 4 + 2], zs[(2 * j) * 4 + 3], As[0][j][1], As[1][j][1]);
                split_pair(zs[(2 * j + 1) * 4 + 0], zs[(2 * j + 1) * 4 + 1], As[0][j][2], As[1][j][2]);
                split_pair(zs[(2 * j + 1) * 4 + 2], zs[(2 * j + 1) * 4 + 3], As[0][j][3], As[1][j][3]);
            }

            // ---- GEMM1: 16x32 @ W1^T -> 16x64 ----
            float D[8][4];
#pragma unroll
            for (int nt = 0; nt < 8; nt++) {
                float2 bb = be1[nt * 32 + lane];
                D[nt][0] = bb.x; D[nt][1] = bb.y; D[nt][2] = bb.x; D[nt][3] = bb.y;
            }
#pragma unroll
            for (int pb = 0; pb < 2; pb++)
#pragma unroll
                for (int nt = 0; nt < 8; nt++) {
                    uint4 Bv = bf1[(pb * 8 + nt) * 32 + lane];
                    mma_bf16(D[nt], As[0][0], Bv.x, Bv.y);
                    mma_bf16(D[nt], As[0][1], Bv.z, Bv.w);
                    if (pb == 0) {
                        mma_bf16(D[nt], As[1][0], Bv.x, Bv.y);
                        mma_bf16(D[nt], As[1][1], Bv.z, Bv.w);
                    }
                }
#pragma unroll
            for (int q = 0; q < 4; q++) {
                float t0 = fast_tanh(D[2 * q][0]), t1 = fast_tanh(D[2 * q][1]);
                split_pair(t0, t1, An[0][q][0], An[1][q][0]);
                t0 = fast_tanh(D[2 * q][2]); t1 = fast_tanh(D[2 * q][3]);
                split_pair(t0, t1, An[0][q][1], An[1][q][1]);
                t0 = fast_tanh(D[2 * q + 1][0]); t1 = fast_tanh(D[2 * q + 1][1]);
                split_pair(t0, t1, An[0][q][2], An[1][q][2]);
                t0 = fast_tanh(D[2 * q + 1][2]); t1 = fast_tanh(D[2 * q + 1][3]);
                split_pair(t0, t1, An[0][q][3], An[1][q][3]);
            }

            // ---- GEMM2: 16x64 @ W2^T -> 16x64 ----
            float E[8][4];
#pragma unroll
            for (int nt = 0; nt < 8; nt++) {
                float2 bb = be2[nt * 32 + lane];
                E[nt][0] = bb.x; E[nt][1] = bb.y; E[nt][2] = bb.x; E[nt][3] = bb.y;
            }
#pragma unroll
            for (int pb = 0; pb < 2; pb++)
#pragma unroll
                for (int kp = 0; kp < 2; kp++)
#pragma unroll
                    for (int nt = 0; nt < 8; nt++) {
                        uint4 Bv = bf2[((pb * 8 + nt) * 2 + kp) * 32 + lane];
                        mma_bf16(E[nt], An[0][2 * kp], Bv.x, Bv.y);
                        mma_bf16(E[nt], An[0][2 * kp + 1], Bv.z, Bv.w);
                        if (pb == 0) {
                            mma_bf16(E[nt], An[1][2 * kp], Bv.x, Bv.y);
                            mma_bf16(E[nt], An[1][2 * kp + 1], Bv.z, Bv.w);
                        }
                    }
#pragma unroll
            for (int q = 0; q < 4; q++) {
                float t0 = fast_tanh(E[2 * q][0]), t1 = fast_tanh(E[2 * q][1]);
                split_pair(t0, t1, As[0][q][0], As[1][q][0]);
                t0 = fast_tanh(E[2 * q][2]); t1 = fast_tanh(E[2 * q][3]);
                split_pair(t0, t1, As[0][q][1], As[1][q][1]);
                t0 = fast_tanh(E[2 * q + 1][0]); t1 = fast_tanh(E[2 * q + 1][1]);
                split_pair(t0, t1, As[0][q][2], As[1][q][2]);
                t0 = fast_tanh(E[2 * q + 1][2]); t1 = fast_tanh(E[2 * q + 1][3]);
                split_pair(t0, t1, As[0][q][3], As[1][q][3]);
            }

            // ---- GEMM3: 16x64 @ W3p^T -> 16x96, per channel group ----
            float kc[4][4];
#pragma unroll
            for (int g = 0; g < 3; g++) {
                float F[4][4];
#pragma unroll
                for (int i = 0; i < 4; i++) {
                    float2 bb = be3[(g * 4 + i) * 32 + lane];
                    F[i][0] = bb.x; F[i][1] = bb.y; F[i][2] = bb.x; F[i][3] = bb.y;
                }
#pragma unroll
                for (int pb = 0; pb < 2; pb++)
#pragma unroll
                    for (int kp = 0; kp < 2; kp++)
#pragma unroll
                        for (int i = 0; i < 4; i++) {
                            uint4 Bv = bf3[((pb * 12 + g * 4 + i) * 2 + kp) * 32 + lane];
                            mma_bf16(F[i], As[0][2 * kp], Bv.x, Bv.y);
                            mma_bf16(F[i], As[0][2 * kp + 1], Bv.z, Bv.w);
                            if (pb == 0) {
                                mma_bf16(F[i], As[1][2 * kp], Bv.x, Bv.y);
                                mma_bf16(F[i], As[1][2 * kp + 1], Bv.z, Bv.w);
                            }
                        }
                float dA = dqA[g], dB = dqB[g];
                if (g == 0) {
#pragma unroll
                    for (int i = 0; i < 4; i++) {
                        kc[i][0] = F[i][0] * dA; kc[i][1] = F[i][1] * dA;
                        kc[i][2] = F[i][2] * dB; kc[i][3] = F[i][3] * dB;
                    }
                } else {
#pragma unroll
                    for (int i = 0; i < 4; i++) {
                        kc[i][0] = fmaf(F[i][0], dA, kc[i][0]); kc[i][1] = fmaf(F[i][1], dA, kc[i][1]);
                        kc[i][2] = fmaf(F[i][2], dB, kc[i][2]); kc[i][3] = fmaf(F[i][3], dB, kc[i][3]);
                    }
                }
            }
            float* kcf = &kc[0][0];

            // ---- Tsit5 stage combine ----
            if (s == 0) {
#pragma unroll
                for (int i = 0; i < 16; i++) { k1[i] = kcf[i]; zs[i] = fmaf(0.161f, kcf[i], z[i]); }
            } else if (s == 1) {
#pragma unroll
                for (int i = 0; i < 16; i++) {
                    k2[i] = kcf[i];
                    zs[i] = fmaf(0.335480655492357f, kcf[i], fmaf(-0.008480655492356989f, k1[i], z[i]));
                }
            } else if (s == 2) {
#pragma unroll
                for (int i = 0; i < 16; i++) {
                    k3[i] = kcf[i];
                    zs[i] = fmaf(4.3622954328695815f, kcf[i], fmaf(-6.359448489975075f, k2[i],
                            fmaf(2.8971530571054935f, k1[i], z[i])));
                }
            } else if (s == 3) {
#pragma unroll
                for (int i = 0; i < 16; i++) {
                    k4[i] = kcf[i];
                    zs[i] = fmaf(-0.09249506636175525f, kcf[i], fmaf(7.4955393428898365f, k3[i],
                            fmaf(-11.748883564062828f, k2[i], fmaf(5.325864828439257f, k1[i], z[i]))));
                }
            } else if (s == 4) {
#pragma unroll
                for (int i = 0; i < 16; i++) {
                    k5[i] = kcf[i];
                    zs[i] = fmaf(-0.028269050394068383f, kcf[i], fmaf(-0.071584973281401f, k4[i],
                            fmaf(8.159367898576159f, k3[i], fmaf(-12.92096931784711f, k2[i],
                            fmaf(5.86145544294642f, k1[i], z[i])))));
                }
            } else {
#pragma unroll
                for (int i = 0; i < 16; i++) {
                    z[i] = fmaf(2.324710524099774f, kcf[i], fmaf(-3.290069515436081f, k5[i],
                           fmaf(1.379008574103742f, k4[i], fmaf(0.4798896504144996f, k3[i],
                           fmaf(0.01f, k2[i], fmaf(0.09646076681806523f, k1[i], z[i]))))));
                }
            }
        }
    }

    // ---- Readout ----
    {
        float pA = 0.f, pB = 0.f;
#pragma unroll
        for (int t = 0; t < 4; t++) {
            int c = 8 * t + 2 * (lane & 3);
            float w0 = w_ro[c], w1v = w_ro[c + 1];
            pA = fmaf(z[t * 4 + 0], w0, fmaf(z[t * 4 + 1], w1v, pA));
            pB = fmaf(z[t * 4 + 2], w0, fmaf(z[t * 4 + 3], w1v, pB));
        }
        pA += __shfl_xor_sync(0xffffffffu, pA, 1);
        pA += __shfl_xor_sync(0xffffffffu, pA, 2);
        pB += __shfl_xor_sync(0xffffffffu, pB, 1);
        pB += __shfl_xor_sync(0xffffffffu, pB, 2);
        float br0 = b_ro[0];
        if ((lane & 3) == 0) {
            if (vA) out[bA] = __fdividef(1.0f, 1.0f + __expf(-(pA + br0)));
            if (vB) out[bB] = __fdividef(1.0f, 1.0f + __expf(-(pB + br0)));
        }
    }
}

extern "C" void kernel_launch(void* const* d_in, const int* in_sizes, int n_in,
                              void* d_out, int out_size) {
    const float* times = (const float*)d_in[0];
    const float* grads = (const float*)d_in[1];
    const float* w1    = (const float*)d_in[2];
    const float* b1    = (const float*)d_in[3];
    const float* w2    = (const float*)d_in[4];
    const float* b2    = (const float*)d_in[5];
    const float* w3    = (const float*)d_in[6];
    const float* b3    = (const float*)d_in[7];
    const float* w_enc = (const float*)d_in[8];
    const float* b_enc = (const float*)d_in[9];
    const float* w_ro  = (const float*)d_in[10];
    const float* b_ro  = (const float*)d_in[11];
    float* out = (float*)d_out;

    int T = in_sizes[0];
    int B = in_sizes[1] / (T * CINC);

    cudaFuncSetAttribute(cde_hmma_kernel, cudaFuncAttributeMaxDynamicSharedMemorySize, SMEM_BYTES);

    int blocks = (B + CTAB - 1) / CTAB;   // 256
    cde_hmma_kernel<<<blocks, NTH, SMEM_BYTES>>>(times, grads, w1, b1, w2, b2, w3, b3,
                                                 w_enc, b_enc, w_ro, b_ro, out, B, T);
}

// round 17
// speedup vs baseline: 1.5064x; 1.5064x over previous
#include <cuda_runtime.h>
#include <cstdint>
#include <cstddef>

#define CINC  3
#define WARPS 4
#define MB    16               // batches per warp (one m16 tile)
#define CTAB  (WARPS * MB)     // 64
#define NTH   (WARPS * 32)

// ---- smem layout (bytes); B-fragments packed as kt-pairs ----
#define BF1_OFF 0              // 8192
#define BF2_OFF 8192           // 16384
#define BF3_OFF 24576          // 24576
#define B1E_OFF 49152          // 2048
#define B2E_OFF 51200          // 2048
#define B3E_OFF 53248          // 3072
#define SMEM_BYTES 56320

__device__ __forceinline__ float hi16f(uint32_t u) { return __uint_as_float(u & 0xFFFF0000u); }

__device__ __forceinline__ uint32_t bf_plane(float v, int p) {
    uint32_t u = __float_as_uint(v);
    if (p == 0) return u >> 16;
    float r = v - hi16f(u);
    return __float_as_uint(r) >> 16;
}

__device__ __forceinline__ void split_pair(float va, float vb, uint32_t& p0, uint32_t& p1) {
    uint32_t Aa = __float_as_uint(va), Ab = __float_as_uint(vb);
    float ra = va - hi16f(Aa), rb = vb - hi16f(Ab);
    uint32_t Ra = __float_as_uint(ra), Rb = __float_as_uint(rb);
    p0 = __byte_perm(Aa, Ab, 0x7632);
    p1 = __byte_perm(Ra, Rb, 0x7632);
}

__device__ __forceinline__ float fast_tanh(float x) {
    float e = __expf(2.0f * x);
    return 1.0f - __fdividef(2.0f, e + 1.0f);
}

__device__ __forceinline__ void mma_bf16(float* d, const uint32_t* a, uint32_t b0, uint32_t b1) {
    asm volatile("mma.sync.aligned.m16n8k16.row.col.f32.bf16.bf16.f32 "
                 "{%0,%1,%2,%3}, {%4,%5,%6,%7}, {%8,%9}, {%0,%1,%2,%3};"
                 : "+f"(d[0]), "+f"(d[1]), "+f"(d[2]), "+f"(d[3])
                 : "r"(a[0]), "r"(a[1]), "r"(a[2]), "r"(a[3]), "r"(b0), "r"(b1));
}

__global__ void __launch_bounds__(NTH, 2) cde_hmma_kernel(
    const float* __restrict__ times,
    const float* __restrict__ grads,
    const float* __restrict__ w1, const float* __restrict__ b1,
    const float* __restrict__ w2, const float* __restrict__ b2,
    const float* __restrict__ w3, const float* __restrict__ b3,
    const float* __restrict__ w_enc, const float* __restrict__ b_enc,
    const float* __restrict__ w_ro, const float* __restrict__ b_ro,
    float* __restrict__ out, int B, int T)
{
    extern __shared__ char sm[];
    int tid = threadIdx.x;
    int lane = tid & 31, warp = tid >> 5;

    // ---- Build packed B-fragment planes + expanded biases in smem ----
    for (int idx = tid; idx < 2 * 8 * 2 * 32; idx += NTH) {
        int ln = idx & 31, f = idx >> 5;
        int kt = f % 2, nt = (f / 2) % 8, p = f / 16;
        int n = nt * 8 + ln / 4, k0 = kt * 16 + 2 * (ln & 3);
        const float* wr = w1 + n * 32;
        uint32_t l0 = bf_plane(wr[k0], p),     l1 = bf_plane(wr[k0 + 1], p);
        uint32_t h0 = bf_plane(wr[k0 + 8], p), h1 = bf_plane(wr[k0 + 9], p);
        ((uint2*)(sm + BF1_OFF))[((p * 8 + nt) * 32 + ln) * 2 + kt] =
            make_uint2(l0 | (l1 << 16), h0 | (h1 << 16));
    }
    for (int idx = tid; idx < 2 * 8 * 4 * 32; idx += NTH) {
        int ln = idx & 31, f = idx >> 5;
        int kt = f % 4, nt = (f / 4) % 8, p = f / 32;
        int n = nt * 8 + ln / 4, k0 = kt * 16 + 2 * (ln & 3);
        const float* wr = w2 + n * 64;
        uint32_t l0 = bf_plane(wr[k0], p),     l1 = bf_plane(wr[k0 + 1], p);
        uint32_t h0 = bf_plane(wr[k0 + 8], p), h1 = bf_plane(wr[k0 + 9], p);
        ((uint2*)(sm + BF2_OFF))[(((p * 8 + nt) * 2 + (kt >> 1)) * 32 + ln) * 2 + (kt & 1)] =
            make_uint2(l0 | (l1 << 16), h0 | (h1 << 16));
    }
    for (int idx = tid; idx < 2 * 12 * 4 * 32; idx += NTH) {
        int ln = idx & 31, f = idx >> 5;
        int kt = f % 4, nt = (f / 4) % 12, p = f / 48;
        int np = nt * 8 + ln / 4;
        int row = 3 * (np & 31) + (np >> 5);      // permuted: logical n' = h + 32*ch
        int k0 = kt * 16 + 2 * (ln & 3);
        const float* wr = w3 + row * 64;
        uint32_t l0 = bf_plane(wr[k0], p),     l1 = bf_plane(wr[k0 + 1], p);
        uint32_t h0 = bf_plane(wr[k0 + 8], p), h1 = bf_plane(wr[k0 + 9], p);
        ((uint2*)(sm + BF3_OFF))[(((p * 12 + nt) * 2 + (kt >> 1)) * 32 + ln) * 2 + (kt & 1)] =
            make_uint2(l0 | (l1 << 16), h0 | (h1 << 16));
    }
    for (int idx = tid; idx < 8 * 32; idx += NTH) {
        int ln = idx & 31, nt = idx >> 5;
        int c = 8 * nt + 2 * (ln & 3);
        ((float2*)(sm + B1E_OFF))[idx] = make_float2(b1[c], b1[c + 1]);
        ((float2*)(sm + B2E_OFF))[idx] = make_float2(b2[c], b2[c + 1]);
    }
    for (int idx = tid; idx < 12 * 32; idx += NTH) {
        int ln = idx & 31, nt = idx >> 5;
        int c = 8 * nt + 2 * (ln & 3);
        int i0 = 3 * (c & 31) + (c >> 5);
        int c1v = c + 1;
        int i1 = 3 * (c1v & 31) + (c1v >> 5);
        ((float2*)(sm + B3E_OFF))[idx] = make_float2(b3[i0], b3[i1]);
    }
    __syncthreads();

    const uint4* bf1 = (const uint4*)(sm + BF1_OFF);
    const uint4* bf2 = (const uint4*)(sm + BF2_OFF);
    const uint4* bf3 = (const uint4*)(sm + BF3_OFF);
    const float2* be1 = (const float2*)(sm + B1E_OFF);
    const float2* be2 = (const float2*)(sm + B2E_OFF);
    const float2* be3 = (const float2*)(sm + B3E_OFF);

    int base = blockIdx.x * CTAB + warp * MB;
    int bA = base + (lane >> 2);
    int bB = bA + 8;
    bool vA = bA < B, vB = bB < B;
    const float* gA = grads + (size_t)(vA ? bA : 0) * (size_t)T * CINC;
    const float* gB = grads + (size_t)(vB ? bB : 0) * (size_t)T * CINC;

    float dt = times[1] - times[0];

    float z[16], k1[16], k2[16], k3[16], k4[16], k5[16], zs[16];
#pragma unroll
    for (int t = 0; t < 4; t++) {
        int c = 8 * t + 2 * (lane & 3);
        float v0 = w_enc[c] + b_enc[c];
        float v1 = w_enc[c + 1] + b_enc[c + 1];
        z[t * 4 + 0] = v0; z[t * 4 + 1] = v1; z[t * 4 + 2] = v0; z[t * 4 + 3] = v1;
    }

    uint32_t As[2][4][4], An[2][4][4];

    float pgA[3], pgB[3];
#pragma unroll
    for (int c = 0; c < 3; c++) { pgA[c] = gA[c]; pgB[c] = gB[c]; }

#pragma unroll 1
    for (int n = 0; n < T - 1; n++) {
        float dqA[3], dqB[3];
#pragma unroll
        for (int c = 0; c < 3; c++) { dqA[c] = pgA[c] * dt; dqB[c] = pgB[c] * dt; }
        int np = (n + 1 < T - 1) ? (n + 1) : n;
#pragma unroll
        for (int c = 0; c < 3; c++) { pgA[c] = gA[np * 3 + c]; pgB[c] = gB[np * 3 + c]; }

#pragma unroll
        for (int i = 0; i < 16; i++) zs[i] = z[i];

#pragma unroll 1
        for (int s = 0; s < 6; s++) {
            // A1 fragments (ktiles 0,1) from zs; lane-local
#pragma unroll
            for (int j = 0; j < 2; j++) {
                split_pair(zs[(2 * j) * 4 + 0], zs[(2 * j) * 4 + 1], As[0][j][0], As[1][j][0]);
                split_pair(zs[(2 * j) * 4 + 2], zs[(2 * j) * 4 + 3], As[0][j][1], As[1][j][1]);
                split_pair(zs[(2 * j + 1) * 4 + 0], zs[(2 * j + 1) * 4 + 1], As[0][j][2], As[1][j][2]);
                split_pair(zs[(2 * j + 1) * 4 + 2], zs[(2 * j + 1) * 4 + 3], As[0][j][3], As[1][j][3]);
            }

            // ---- GEMM1: 16x32 @ W1^T -> 16x64 (8 concurrent accumulator chains) ----
            float D[8][4];
#pragma unroll
            for (int nt = 0; nt < 8; nt++) {
                float2 bb = be1[nt * 32 + lane];
                D[nt][0] = bb.x; D[nt][1] = bb.y; D[nt][2] = bb.x; D[nt][3] = bb.y;
            }
#pragma unroll
            for (int pb = 0; pb < 2; pb++)
#pragma unroll
                for (int nt = 0; nt < 8; nt++) {
                    uint4 Bv = bf1[(pb * 8 + nt) * 32 + lane];
                    mma_bf16(D[nt], As[0][0], Bv.x, Bv.y);
                    mma_bf16(D[nt], As[0][1], Bv.z, Bv.w);
                    if (pb == 0) {
                        mma_bf16(D[nt], As[1][0], Bv.x, Bv.y);
                        mma_bf16(D[nt], As[1][1], Bv.z, Bv.w);
                    }
                }
#pragma unroll
            for (int q = 0; q < 4; q++) {
                float t0 = fast_tanh(D[2 * q][0]), t1 = fast_tanh(D[2 * q][1]);
                split_pair(t0, t1, An[0][q][0], An[1][q][0]);
                t0 = fast_tanh(D[2 * q][2]); t1 = fast_tanh(D[2 * q][3]);
                split_pair(t0, t1, An[0][q][1], An[1][q][1]);
                t0 = fast_tanh(D[2 * q + 1][0]); t1 = fast_tanh(D[2 * q + 1][1]);
                split_pair(t0, t1, An[0][q][2], An[1][q][2]);
                t0 = fast_tanh(D[2 * q + 1][2]); t1 = fast_tanh(D[2 * q + 1][3]);
                split_pair(t0, t1, An[0][q][3], An[1][q][3]);
            }

            // ---- GEMM2: 16x64 @ W2^T -> 16x64 (8 concurrent chains) ----
            float E[8][4];
#pragma unroll
            for (int nt = 0; nt < 8; nt++) {
                float2 bb = be2[nt * 32 + lane];
                E[nt][0] = bb.x; E[nt][1] = bb.y; E[nt][2] = bb.x; E[nt][3] = bb.y;
            }
#pragma unroll
            for (int pb = 0; pb < 2; pb++)
#pragma unroll
                for (int kp = 0; kp < 2; kp++)
#pragma unroll
                    for (int nt = 0; nt < 8; nt++) {
                        uint4 Bv = bf2[((pb * 8 + nt) * 2 + kp) * 32 + lane];
                        mma_bf16(E[nt], An[0][2 * kp], Bv.x, Bv.y);
                        mma_bf16(E[nt], An[0][2 * kp + 1], Bv.z, Bv.w);
                        if (pb == 0) {
                            mma_bf16(E[nt], An[1][2 * kp], Bv.x, Bv.y);
                            mma_bf16(E[nt], An[1][2 * kp + 1], Bv.z, Bv.w);
                        }
                    }
#pragma unroll
            for (int q = 0; q < 4; q++) {
                float t0 = fast_tanh(E[2 * q][0]), t1 = fast_tanh(E[2 * q][1]);
                split_pair(t0, t1, As[0][q][0], As[1][q][0]);
                t0 = fast_tanh(E[2 * q][2]); t1 = fast_tanh(E[2 * q][3]);
                split_pair(t0, t1, As[0][q][1], As[1][q][1]);
                t0 = fast_tanh(E[2 * q + 1][0]); t1 = fast_tanh(E[2 * q + 1][1]);
                split_pair(t0, t1, As[0][q][2], As[1][q][2]);
                t0 = fast_tanh(E[2 * q + 1][2]); t1 = fast_tanh(E[2 * q + 1][3]);
                split_pair(t0, t1, As[0][q][3], As[1][q][3]);
            }

            // ---- GEMM3: 16x64 @ W3p^T -> 16x96; ALL 12 accumulator chains live ----
            // (was 3 sequential groups of 4 chains — too few chains to cover HMMA
            //  RAW latency; 12 concurrent chains keep the tensor pipe fed)
            float F[12][4];
#pragma unroll
            for (int i = 0; i < 12; i++) {
                float2 bb = be3[i * 32 + lane];
                F[i][0] = bb.x; F[i][1] = bb.y; F[i][2] = bb.x; F[i][3] = bb.y;
            }
#pragma unroll
            for (int pb = 0; pb < 2; pb++)
#pragma unroll
                for (int kp = 0; kp < 2; kp++)
#pragma unroll
                    for (int i = 0; i < 12; i++) {
                        uint4 Bv = bf3[((pb * 12 + i) * 2 + kp) * 32 + lane];
                        mma_bf16(F[i], As[0][2 * kp], Bv.x, Bv.y);
                        mma_bf16(F[i], As[0][2 * kp + 1], Bv.z, Bv.w);
                        if (pb == 0) {
                            mma_bf16(F[i], As[1][2 * kp], Bv.x, Bv.y);
                            mma_bf16(F[i], As[1][2 * kp + 1], Bv.z, Bv.w);
                        }
                    }
            // contract with dq: chain g*4+i belongs to channel g
            float kc[4][4];
#pragma unroll
            for (int i = 0; i < 4; i++) {
                kc[i][0] = F[i][0] * dqA[0];
                kc[i][1] = F[i][1] * dqA[0];
                kc[i][2] = F[i][2] * dqB[0];
                kc[i][3] = F[i][3] * dqB[0];
                kc[i][0] = fmaf(F[4 + i][0], dqA[1], kc[i][0]);
                kc[i][1] = fmaf(F[4 + i][1], dqA[1], kc[i][1]);
                kc[i][2] = fmaf(F[4 + i][2], dqB[1], kc[i][2]);
                kc[i][3] = fmaf(F[4 + i][3], dqB[1], kc[i][3]);
                kc[i][0] = fmaf(F[8 + i][0], dqA[2], kc[i][0]);
                kc[i][1] = fmaf(F[8 + i][1], dqA[2], kc[i][1]);
                kc[i][2] = fmaf(F[8 + i][2], dqB[2], kc[i][2]);
                kc[i][3] = fmaf(F[8 + i][3], dqB[2], kc[i][3]);
            }
            float* kcf = &kc[0][0];

            // ---- Tsit5 stage combine ----
            if (s == 0) {
#pragma unroll
                for (int i = 0; i < 16; i++) { k1[i] = kcf[i]; zs[i] = fmaf(0.161f, kcf[i], z[i]); }
            } else if (s == 1) {
#pragma unroll
                for (int i = 0; i < 16; i++) {
                    k2[i] = kcf[i];
                    zs[i] = fmaf(0.335480655492357f, kcf[i], fmaf(-0.008480655492356989f, k1[i], z[i]));
                }
            } else if (s == 2) {
#pragma unroll
                for (int i = 0; i < 16; i++) {
                    k3[i] = kcf[i];
                    zs[i] = fmaf(4.3622954328695815f, kcf[i], fmaf(-6.359448489975075f, k2[i],
                            fmaf(2.8971530571054935f, k1[i], z[i])));
                }
            } else if (s == 3) {
#pragma unroll
                for (int i = 0; i < 16; i++) {
                    k4[i] = kcf[i];
                    zs[i] = fmaf(-0.09249506636175525f, kcf[i], fmaf(7.4955393428898365f, k3[i],
                            fmaf(-11.748883564062828f, k2[i], fmaf(5.325864828439257f, k1[i], z[i]))));
                }
            } else if (s == 4) {
#pragma unroll
                for (int i = 0; i < 16; i++) {
                    k5[i] = kcf[i];
                    zs[i] = fmaf(-0.028269050394068383f, kcf[i], fmaf(-0.071584973281401f, k4[i],
                            fmaf(8.159367898576159f, k3[i], fmaf(-12.92096931784711f, k2[i],
                            fmaf(5.86145544294642f, k1[i], z[i])))));
                }
            } else {
#pragma unroll
                for (int i = 0; i < 16; i++) {
                    z[i] = fmaf(2.324710524099774f, kcf[i], fmaf(-3.290069515436081f, k5[i],
                           fmaf(1.379008574103742f, k4[i], fmaf(0.4798896504144996f, k3[i],
                           fmaf(0.01f, k2[i], fmaf(0.09646076681806523f, k1[i], z[i]))))));
                }
            }
        }
    }

    // ---- Readout ----
    {
        float pA = 0.f, pB = 0.f;
#pragma unroll
        for (int t = 0; t < 4; t++) {
            int c = 8 * t + 2 * (lane & 3);
            float w0 = w_ro[c], w1v = w_ro[c + 1];
            pA = fmaf(z[t * 4 + 0], w0, fmaf(z[t * 4 + 1], w1v, pA));
            pB = fmaf(z[t * 4 + 2], w0, fmaf(z[t * 4 + 3], w1v, pB));
        }
        pA += __shfl_xor_sync(0xffffffffu, pA, 1);
        pA += __shfl_xor_sync(0xffffffffu, pA, 2);
        pB += __shfl_xor_sync(0xffffffffu, pB, 1);
        pB += __shfl_xor_sync(0xffffffffu, pB, 2);
        float br0 = b_ro[0];
        if ((lane & 3) == 0) {
            if (vA) out[bA] = __fdividef(1.0f, 1.0f + __expf(-(pA + br0)));
            if (vB) out[bB] = __fdividef(1.0f, 1.0f + __expf(-(pB + br0)));
        }
    }
}

extern "C" void kernel_launch(void* const* d_in, const int* in_sizes, int n_in,
                              void* d_out, int out_size) {
    const float* times = (const float*)d_in[0];
    const float* grads = (const float*)d_in[1];
    const float* w1    = (const float*)d_in[2];
    const float* b1    = (const float*)d_in[3];
    const float* w2    = (const float*)d_in[4];
    const float* b2    = (const float*)d_in[5];
    const float* w3    = (const float*)d_in[6];
    const float* b3    = (const float*)d_in[7];
    const float* w_enc = (const float*)d_in[8];
    const float* b_enc = (const float*)d_in[9];
    const float* w_ro  = (const float*)d_in[10];
    const float* b_ro  = (const float*)d_in[11];
    float* out = (float*)d_out;

    int T = in_sizes[0];
    int B = in_sizes[1] / (T * CINC);

    cudaFuncSetAttribute(cde_hmma_kernel, cudaFuncAttributeMaxDynamicSharedMemorySize, SMEM_BYTES);

    int blocks = (B + CTAB - 1) / CTAB;   // 256
    cde_hmma_kernel<<<blocks, NTH, SMEM_BYTES>>>(times, grads, w1, b1, w2, b2, w3, b3,
                                                 w_enc, b_enc, w_ro, b_ro, out, B, T);
}